// round 1
// baseline (speedup 1.0000x reference)
#include <cuda_runtime.h>
#include <cstdint>

// Chamfer loss: B=16, N=4096, C=6 (first 3 channels used).
// loss = mean_{b,j} min_i pdist[b,i,j] + mean_{b,i} min_j pdist[b,i,j]
// pdist = |q|^2 + |r|^2 - 2 q.r  (symmetric), fold |q|^2 out of inner loop.

#define BATCH 16
#define NPTS  4096
#define CSTR  6
#define THREADS 128
#define IPT 4          // query points per thread
#define JT  2048       // ref points per smem tile (32 KB of float4)

__device__ float g_acc;

__global__ void k_zero() { g_acc = 0.0f; }

__global__ void k_final(float* out) {
    out[0] = g_acc * (1.0f / (float)(BATCH * NPTS));
}

__global__ void __launch_bounds__(THREADS)
k_chamfer(const float* __restrict__ x, const float* __restrict__ y) {
    __shared__ float4 sy[JT];
    __shared__ float ws[THREADS / 32];

    const int bid  = blockIdx.x;          // 0..255
    const int dir  = bid >> 7;            // 0: query=x ref=y ; 1: query=y ref=x
    const int t    = bid & 127;
    const int b    = t >> 3;              // batch
    const int tile = t & 7;               // i-tile within batch (8 tiles of 512)

    const float* q = dir ? y : x;
    const float* r = dir ? x : y;
    const float* qb = q + (size_t)b * NPTS * CSTR;
    const float* rb = r + (size_t)b * NPTS * CSTR;

    const int tid = threadIdx.x;

    float qx[IPT], qy[IPT], qz[IPT], rq[IPT], mn[IPT];
    const int i0 = tile * (THREADS * IPT) + tid * IPT;
#pragma unroll
    for (int k = 0; k < IPT; k++) {
        const float* p = qb + (size_t)(i0 + k) * CSTR;
        qx[k] = p[0]; qy[k] = p[1]; qz[k] = p[2];
        rq[k] = qx[k] * qx[k] + qy[k] * qy[k] + qz[k] * qz[k];
        mn[k] = 3.4e38f;
    }

    for (int jc = 0; jc < NPTS; jc += JT) {
        __syncthreads();
        for (int j = tid; j < JT; j += THREADS) {
            const float* p = rb + (size_t)(jc + j) * CSTR;
            float a = p[0], bb = p[1], c = p[2];
            sy[j] = make_float4(a, bb, c, fmaf(a, a, fmaf(bb, bb, c * c)));
        }
        __syncthreads();

#pragma unroll 4
        for (int j = 0; j < JT; j++) {
            float4 v = sy[j];
#pragma unroll
            for (int k = 0; k < IPT; k++) {
                float dot = fmaf(qx[k], v.x, fmaf(qy[k], v.y, qz[k] * v.z));
                mn[k] = fminf(mn[k], fmaf(-2.0f, dot, v.w));
            }
        }
    }

    float local = 0.0f;
#pragma unroll
    for (int k = 0; k < IPT; k++) local += rq[k] + mn[k];

    // warp reduce
#pragma unroll
    for (int o = 16; o > 0; o >>= 1)
        local += __shfl_xor_sync(0xffffffffu, local, o);
    if ((tid & 31) == 0) ws[tid >> 5] = local;
    __syncthreads();
    if (tid == 0) {
        float s = 0.0f;
#pragma unroll
        for (int w = 0; w < THREADS / 32; w++) s += ws[w];
        atomicAdd(&g_acc, s);
    }
}

extern "C" void kernel_launch(void* const* d_in, const int* in_sizes, int n_in,
                              void* d_out, int out_size) {
    const float* x = (const float*)d_in[0];
    const float* y = (const float*)d_in[1];
    float* out = (float*)d_out;
    (void)in_sizes; (void)n_in; (void)out_size;

    k_zero<<<1, 1>>>();
    k_chamfer<<<2 * BATCH * (NPTS / (THREADS * IPT)), THREADS>>>(x, y);
    k_final<<<1, 1>>>(out);
}

// round 2
// speedup vs baseline: 1.3914x; 1.3914x over previous
#include <cuda_runtime.h>
#include <cstdint>

// Chamfer loss: B=16, N=4096, C=6 (first 3 channels used).
// d(i,j) = |q_i|^2 + [ |r_j|^2 - 2 q_i . r_j ]
// Ref tile prescaled to (-2r0,-2r1,-2r2, |r|^2) -> 3 FMA per pair.
// Two j-points packed per 64-bit reg, processed with fma.rn.f32x2 (FFMA2).

#define BATCH 16
#define NPTS  4096
#define CSTR  6
#define THREADS 128
#define IPT 4           // query points per thread
#define JT  2048        // ref points per smem tile
#define J2  (JT / 2)    // packed pairs per tile

__device__ float g_acc;   // zero-initialized; k_final resets it after reading

__global__ void k_final(float* out) {
    out[0] = g_acc * (1.0f / (float)(BATCH * NPTS));
    g_acc = 0.0f;         // restore invariant for next graph replay
}

__device__ __forceinline__ unsigned long long pk2(float lo, float hi) {
    unsigned long long r;
    asm("mov.b64 %0, {%1, %2};" : "=l"(r) : "f"(lo), "f"(hi));
    return r;
}
__device__ __forceinline__ unsigned long long fma2(unsigned long long a,
                                                   unsigned long long b,
                                                   unsigned long long c) {
    unsigned long long d;
    asm("fma.rn.f32x2 %0, %1, %2, %3;" : "=l"(d) : "l"(a), "l"(b), "l"(c));
    return d;
}
__device__ __forceinline__ void upk2(unsigned long long v, float& lo, float& hi) {
    asm("mov.b64 {%0, %1}, %2;" : "=f"(lo), "=f"(hi) : "l"(v));
}

__global__ void __launch_bounds__(THREADS)
k_chamfer(const float* __restrict__ x, const float* __restrict__ y) {
    // s_a[j].x = {-2rx(2j), -2rx(2j+1)}   s_a[j].y = {-2ry(2j), -2ry(2j+1)}
    // s_b[j].x = {-2rz(2j), -2rz(2j+1)}   s_b[j].y = {rr(2j),   rr(2j+1)}
    __shared__ ulonglong2 s_a[J2];
    __shared__ ulonglong2 s_b[J2];
    __shared__ float ws[THREADS / 32];

    const int bid  = blockIdx.x;          // 0..255
    const int dir  = bid >> 7;
    const int t    = bid & 127;
    const int b    = t >> 3;              // batch
    const int tile = t & 7;               // i-tile (8 tiles of 512)

    const float* q  = dir ? y : x;
    const float* r  = dir ? x : y;
    const float* qb = q + (size_t)b * NPTS * CSTR;
    const float* rb = r + (size_t)b * NPTS * CSTR;

    const int tid = threadIdx.x;

    unsigned long long qx2[IPT], qy2[IPT], qz2[IPT];
    float rq[IPT], mnl[IPT], mnh[IPT];
    const int i0 = tile * (THREADS * IPT) + tid * IPT;
#pragma unroll
    for (int k = 0; k < IPT; k++) {
        const float* p = qb + (size_t)(i0 + k) * CSTR;
        float a = p[0], bb = p[1], c = p[2];
        rq[k]  = fmaf(a, a, fmaf(bb, bb, c * c));
        qx2[k] = pk2(a, a);
        qy2[k] = pk2(bb, bb);
        qz2[k] = pk2(c, c);
        mnl[k] = 3.4e38f;
        mnh[k] = 3.4e38f;
    }

    for (int jc = 0; jc < NPTS; jc += JT) {
        __syncthreads();
        for (int j = tid; j < J2; j += THREADS) {
            const float* p = rb + (size_t)(jc + 2 * j) * CSTR;
            float a0 = p[0], b0 = p[1], c0 = p[2];
            float a1 = p[6], b1 = p[7], c1 = p[8];
            float rr0 = fmaf(a0, a0, fmaf(b0, b0, c0 * c0));
            float rr1 = fmaf(a1, a1, fmaf(b1, b1, c1 * c1));
            ulonglong2 va, vb;
            va.x = pk2(-2.0f * a0, -2.0f * a1);
            va.y = pk2(-2.0f * b0, -2.0f * b1);
            vb.x = pk2(-2.0f * c0, -2.0f * c1);
            vb.y = pk2(rr0, rr1);
            s_a[j] = va;
            s_b[j] = vb;
        }
        __syncthreads();

#pragma unroll 4
        for (int j = 0; j < J2; j++) {
            ulonglong2 va = s_a[j];
            ulonglong2 vb = s_b[j];
#pragma unroll
            for (int k = 0; k < IPT; k++) {
                unsigned long long d =
                    fma2(qx2[k], va.x, fma2(qy2[k], va.y, fma2(qz2[k], vb.x, vb.y)));
                float dl, dh;
                upk2(d, dl, dh);
                mnl[k] = fminf(mnl[k], dl);
                mnh[k] = fminf(mnh[k], dh);
            }
        }
    }

    float local = 0.0f;
#pragma unroll
    for (int k = 0; k < IPT; k++)
        local += rq[k] + fminf(mnl[k], mnh[k]);

    // warp + block reduce, then one atomic per block
#pragma unroll
    for (int o = 16; o > 0; o >>= 1)
        local += __shfl_xor_sync(0xffffffffu, local, o);
    if ((tid & 31) == 0) ws[tid >> 5] = local;
    __syncthreads();
    if (tid == 0) {
        float s = 0.0f;
#pragma unroll
        for (int w = 0; w < THREADS / 32; w++) s += ws[w];
        atomicAdd(&g_acc, s);
    }
}

extern "C" void kernel_launch(void* const* d_in, const int* in_sizes, int n_in,
                              void* d_out, int out_size) {
    const float* x = (const float*)d_in[0];
    const float* y = (const float*)d_in[1];
    float* out = (float*)d_out;
    (void)in_sizes; (void)n_in; (void)out_size;

    k_chamfer<<<2 * BATCH * (NPTS / (THREADS * IPT)), THREADS>>>(x, y);
    k_final<<<1, 1>>>(out);
}